// round 15
// baseline (speedup 1.0000x reference)
#include <cuda_runtime.h>
#include <cuda_fp16.h>
#include <cstdint>

typedef unsigned long long ull;
#define FULLMASK 0xFFFFFFFFu

// Scratch for combined features [vx,vy,vz, rx,ry,rz] per row (64*1024 rows).
__device__ float g_comb[64 * 1024 * 6];

// Prepped W2 (B = W2[k][n]) as mma.sync m16n8k16 B-fragment images, fp16 hi/lo.
__device__ __align__(16) unsigned char g_bhi[2 * 4 * 16384];
__device__ __align__(16) unsigned char g_blo[2 * 4 * 16384];

// ---------------------------------------------------------------------------
// Kernel 0: prep W2 -> fp16 hi/lo B-fragment images (runs once per launch).
// ---------------------------------------------------------------------------
__device__ __forceinline__ uint32_t pkh2(float lo, float hi) {
    uint32_t r;
    asm("cvt.rn.f16x2.f32 %0, %1, %2;" : "=r"(r) : "f"(hi), "f"(lo));
    return r;
}
__device__ __forceinline__ void splitf(float x, float &hi, float &lo) {
    __half h = __float2half_rn(x);
    hi = __half2float(h);
    lo = x - hi;
}

__global__ void __launch_bounds__(256) w2prep_kernel(const float* __restrict__ W2) {
    const int gid = blockIdx.x * 256 + threadIdx.x;   // 0..16383
    const int lane = gid & 31;
    const int nf = (gid >> 5) & 31;
    const int kk = gid >> 10;                          // 0..15
    const int k0 = kk * 16 + (lane & 3) * 2;
    const int n  = nf * 8 + (lane >> 2);
    float w00 = W2[(k0 + 0) * 256 + n];
    float w01 = W2[(k0 + 1) * 256 + n];
    float w10 = W2[(k0 + 8) * 256 + n];
    float w11 = W2[(k0 + 9) * 256 + n];
    float h00, l00, h01, l01, h10, l10, h11, l11;
    splitf(w00, h00, l00); splitf(w01, h01, l01);
    splitf(w10, h10, l10); splitf(w11, h11, l11);
    const int nh = nf >> 4, c = kk >> 2, kkc = kk & 3, nfh = nf & 15;
    const size_t off = (size_t)(nh * 4 + c) * 16384
                     + (size_t)(((kkc * 16 + nfh) * 32 + lane) * 8);
    *(uint2*)(g_bhi + off) = make_uint2(pkh2(h00, h01), pkh2(h10, h11));
    *(uint2*)(g_blo + off) = make_uint2(pkh2(l00, l01), pkh2(l10, l11));
}

// ---------------------------------------------------------------------------
// noop: window spacers so topk_kernel is the 4th launch (= the one ncu
// captures, per R8-R14 observation). Remove once topk is tuned.
// ---------------------------------------------------------------------------
__global__ void noop_kernel() {}

// ---------------------------------------------------------------------------
// Kernel 1: top-4 smallest distances per row -> combined features.
// (FROZEN from R14 for clean profiling: lane-per-row, cp.async 4-stage
// pipeline on 32x32 tiles, fp32 prefilter guarding exact u64 insert.)
// ---------------------------------------------------------------------------

__device__ __forceinline__ void cswap_u64(ull &a, ull &b) {
    if (b < a) { ull t = a; a = b; b = t; }
}

#define TKW 2           // warps per block
#define TK_ST 4         // pipeline stages
#define TK_TILES 32     // 1024 cols / 32

__global__ void __launch_bounds__(TKW * 32) topk_kernel(
    const float* __restrict__ dm, const float* __restrict__ vel)
{
    __shared__ float4 tile[TKW][TK_ST][32 * 9];

    const int warp = threadIdx.x >> 5;
    const int lane = threadIdx.x & 31;
    const int row0 = (blockIdx.x * TKW + warp) * 32;
    const int myrow = row0 + lane;
    const float* base = dm + (size_t)row0 * 1024;

    const ull INIT = ((ull)0x7F800000u << 32) | 0xFFFFFFFFull;
    ull k0 = INIT, k1 = INIT, k2 = INIT, k3 = INIT;
    float t3f = __int_as_float(0x7F800000);

    uint32_t sbase = (uint32_t)__cvta_generic_to_shared(&tile[warp][0][0]);

    #pragma unroll
    for (int p = 0; p < TK_ST - 1; p++) {
        uint32_t dst = sbase + (uint32_t)p * (32 * 9 * 16);
        #pragma unroll
        for (int i = 0; i < 8; i++) {
            const int ch = lane + 32 * i;
            const int r = ch >> 3, cc = ch & 7;
            const float* src = base + (size_t)r * 1024 + p * 32 + cc * 4;
            asm volatile("cp.async.cg.shared.global [%0], [%1], 16;"
                         :: "r"(dst + (uint32_t)(r * 9 + cc) * 16u), "l"(src)
                         : "memory");
        }
        asm volatile("cp.async.commit_group;" ::: "memory");
    }

    #pragma unroll 1
    for (int t = 0; t < TK_TILES; t++) {
        if (t + 3 < TK_TILES) {
            const int p = t + 3;
            uint32_t dst = sbase + (uint32_t)(p & (TK_ST - 1)) * (32 * 9 * 16);
            #pragma unroll
            for (int i = 0; i < 8; i++) {
                const int ch = lane + 32 * i;
                const int r = ch >> 3, cc = ch & 7;
                const float* src = base + (size_t)r * 1024 + p * 32 + cc * 4;
                asm volatile("cp.async.cg.shared.global [%0], [%1], 16;"
                             :: "r"(dst + (uint32_t)(r * 9 + cc) * 16u), "l"(src)
                             : "memory");
            }
            asm volatile("cp.async.commit_group;" ::: "memory");
            asm volatile("cp.async.wait_group 3;" ::: "memory");
        } else if (t + 3 == TK_TILES) {
            asm volatile("cp.async.wait_group 2;" ::: "memory");
        } else if (t + 2 == TK_TILES) {
            asm volatile("cp.async.wait_group 1;" ::: "memory");
        } else {
            asm volatile("cp.async.wait_group 0;" ::: "memory");
        }
        __syncwarp();

        const float4* myr = &tile[warp][t & (TK_ST - 1)][lane * 9];
        #pragma unroll
        for (int c = 0; c < 8; c++) {
            float4 v = myr[c];
            float mn = fminf(fminf(v.x, v.y), fminf(v.z, v.w));
            if (mn <= t3f) {
                const int jb = t * 32 + c * 4;
                float e[4] = {v.x, v.y, v.z, v.w};
                #pragma unroll
                for (int q = 0; q < 4; q++) {
                    if (e[q] <= t3f) {
                        ull key = ((ull)__float_as_uint(e[q]) << 32) | (unsigned)(jb + q);
                        if (key < k3) {
                            k3 = key;
                            cswap_u64(k2, k3);
                            cswap_u64(k1, k2);
                            cswap_u64(k0, k1);
                            t3f = __uint_as_float((unsigned)(k3 >> 32));
                        }
                    }
                }
            }
        }
        __syncwarp();
    }

    {
        const int b = myrow >> 10;
        const int a = myrow & 1023;
        const float* vb = vel + (size_t)b * (1024 * 3);
        const int i1 = (int)(unsigned)k1;
        const int i2 = (int)(unsigned)k2;
        const int i3 = (int)(unsigned)k3;
        float sx = vb[a * 3 + 0], sy = vb[a * 3 + 1], sz = vb[a * 3 + 2];
        float nx = vb[i1 * 3 + 0] + vb[i2 * 3 + 0] + vb[i3 * 3 + 0];
        float ny = vb[i1 * 3 + 1] + vb[i2 * 3 + 1] + vb[i3 * 3 + 1];
        float nz = vb[i1 * 3 + 2] + vb[i2 * 3 + 2] + vb[i3 * 3 + 2];
        const float third = 1.0f / 3.0f;
        float* c = g_comb + (size_t)myrow * 6;
        c[0] = sx; c[1] = sy; c[2] = sz;
        c[3] = sx - nx * third;
        c[4] = sy - ny * third;
        c[5] = sz - nz * third;
    }
}

// ---------------------------------------------------------------------------
// Kernel 2: fused MLP, 2-MMA fp16 split GEMM2; B-chunk images now DOUBLE-
// BUFFERED via cp.async: chunk 0 copy overlaps phase A, chunk c+1 overlaps
// chunk c's MMAs (previously 4 exposed 64KB copy bubbles per block).
// ---------------------------------------------------------------------------

#define AS_U32 132
#define A_BYTES (128 * AS_U32 * 4)

#define OFF_W1   0
#define OFF_B1   6144
#define OFF_G    7168
#define OFF_BT   8192
#define OFF_B2   9216
#define OFF_CMB  10240
#define OFF_AHI  13312
#define OFF_B    (OFF_AHI + A_BYTES)     // 80896: 2 buffers x 64KB
#define SMEM_MLP (OFF_B + 131072)        // 211968

__device__ __forceinline__ void mma_hff(float d[4], const uint32_t a[4],
                                        uint32_t b0, uint32_t b1) {
    asm volatile(
        "mma.sync.aligned.m16n8k16.row.col.f32.f16.f16.f32 "
        "{%0,%1,%2,%3}, {%4,%5,%6,%7}, {%8,%9}, {%0,%1,%2,%3};"
        : "+f"(d[0]), "+f"(d[1]), "+f"(d[2]), "+f"(d[3])
        : "r"(a[0]), "r"(a[1]), "r"(a[2]), "r"(a[3]), "r"(b0), "r"(b1));
}

// issue async copy of k-chunk c's four 16KB B images into buffer buf
__device__ __forceinline__ void issue_b_chunk(char* smc, int c, int buf, int t) {
    const unsigned char* srcs[4] = {
        g_bhi + (size_t)c * 16384,        // nh0 hi
        g_blo + (size_t)c * 16384,        // nh0 lo
        g_bhi + (size_t)(4 + c) * 16384,  // nh1 hi
        g_blo + (size_t)(4 + c) * 16384   // nh1 lo
    };
    uint32_t dstb = (uint32_t)__cvta_generic_to_shared(smc + OFF_B)
                  + (uint32_t)buf * 65536u + (uint32_t)t * 32u;
    #pragma unroll
    for (int img = 0; img < 4; img++) {
        const unsigned char* s = srcs[img] + t * 32;
        uint32_t d = dstb + (uint32_t)img * 16384u;
        asm volatile("cp.async.cg.shared.global [%0], [%1], 16;"
                     :: "r"(d), "l"(s) : "memory");
        asm volatile("cp.async.cg.shared.global [%0], [%1], 16;"
                     :: "r"(d + 16u), "l"(s + 16) : "memory");
    }
    asm volatile("cp.async.commit_group;" ::: "memory");
}

__global__ void __launch_bounds__(512) mlp_kernel(
    const float* __restrict__ W1, const float* __restrict__ b1,
    const float* __restrict__ gamma, const float* __restrict__ beta,
    const float* __restrict__ b2, float* __restrict__ out)
{
    extern __shared__ char smc[];
    float* smf = (float*)smc;

    const int t = threadIdx.x;
    const int wid = t >> 5;
    const int lane = t & 31;
    const int row0 = blockIdx.x * 128;

    // kick off chunk 0's B copy immediately (overlaps everything below)
    issue_b_chunk(smc, 0, 0, t);

    for (int i = t; i < 6 * 256; i += 512) smf[OFF_W1 / 4 + i] = W1[i];
    if (t < 256) {
        smf[OFF_B1 / 4 + t] = b1[t];
        smf[OFF_G  / 4 + t] = gamma[t];
        smf[OFF_BT / 4 + t] = beta[t];
        smf[OFF_B2 / 4 + t] = b2[t];
    }
    for (int i = t; i < 128 * 6; i += 512)
        smf[OFF_CMB / 4 + i] = g_comb[(size_t)row0 * 6 + i];
    __syncthreads();

    // ---- Phase A: GEMM1+relu (x in regs), LN, fp16 -> smem (hi only)
    {
        const int r = t >> 2;
        const int q = t & 3;
        const float* cm = smf + OFF_CMB / 4 + r * 6;
        const float c0 = cm[0], c1 = cm[1], c2 = cm[2];
        const float c3 = cm[3], c4 = cm[4], c5 = cm[5];
        const float2* w1v = (const float2*)(smc + OFF_W1);
        const float2* b1v = (const float2*)(smc + OFF_B1);

        float xs0[32], xs1[32];
        float sum = 0.f, sq = 0.f;
        #pragma unroll
        for (int pe = 0; pe < 32; pe++) {
            const int pidx = 4 * pe + q;
            float2 bp = b1v[pidx];
            float x0 = bp.x, x1 = bp.y;
            float2 w;
            w = w1v[0 * 128 + pidx]; x0 = fmaf(c0, w.x, x0); x1 = fmaf(c0, w.y, x1);
            w = w1v[1 * 128 + pidx]; x0 = fmaf(c1, w.x, x0); x1 = fmaf(c1, w.y, x1);
            w = w1v[2 * 128 + pidx]; x0 = fmaf(c2, w.x, x0); x1 = fmaf(c2, w.y, x1);
            w = w1v[3 * 128 + pidx]; x0 = fmaf(c3, w.x, x0); x1 = fmaf(c3, w.y, x1);
            w = w1v[4 * 128 + pidx]; x0 = fmaf(c4, w.x, x0); x1 = fmaf(c4, w.y, x1);
            w = w1v[5 * 128 + pidx]; x0 = fmaf(c5, w.x, x0); x1 = fmaf(c5, w.y, x1);
            x0 = fmaxf(x0, 0.f);
            x1 = fmaxf(x1, 0.f);
            sum += x0 + x1;
            sq = fmaf(x0, x0, fmaf(x1, x1, sq));
            xs0[pe] = x0;
            xs1[pe] = x1;
        }
        sum += __shfl_xor_sync(FULLMASK, sum, 1);
        sq  += __shfl_xor_sync(FULLMASK, sq, 1);
        sum += __shfl_xor_sync(FULLMASK, sum, 2);
        sq  += __shfl_xor_sync(FULLMASK, sq, 2);
        const float mu   = sum * (1.f / 256.f);
        const float var  = sq * (1.f / 256.f) - mu * mu;
        const float rstd = rsqrtf(var + 1e-5f);

        const float2* gv2 = (const float2*)(smc + OFF_G);
        const float2* bt2 = (const float2*)(smc + OFF_BT);
        uint32_t* ahi = (uint32_t*)(smc + OFF_AHI) + r * AS_U32;
        #pragma unroll
        for (int pe = 0; pe < 32; pe++) {
            const int pidx = 4 * pe + q;
            float2 gp = gv2[pidx];
            float2 tp = bt2[pidx];
            float y0 = fmaf((xs0[pe] - mu) * rstd, gp.x, tp.x);
            float y1 = fmaf((xs1[pe] - mu) * rstd, gp.y, tp.y);
            ahi[pidx] = pkh2(y0, y1);
        }
    }

    // ---- Phase B: out = h @ W2 + b2 (2 MMAs: ah*bh + ah*bl), B double-buffered
    const int wp = wid & 7;
    const int nh = wid >> 3;
    const uint32_t* Ahi = (const uint32_t*)(smc + OFF_AHI) + wp * 16 * AS_U32;
    const int arow = (lane >> 2);
    const int acol = (lane & 3);

    float acc[16][4];
    #pragma unroll
    for (int nf = 0; nf < 16; nf++)
        #pragma unroll
        for (int j = 0; j < 4; j++) acc[nf][j] = 0.f;

    #pragma unroll 1
    for (int c = 0; c < 4; c++) {
        __syncthreads();   // phase A done (c=0) / MMAs on overwritten buf done (c>=2)
        if (c < 3) {
            issue_b_chunk(smc, c + 1, (c + 1) & 1, t);
            asm volatile("cp.async.wait_group 1;" ::: "memory");  // chunk c done
        } else {
            asm volatile("cp.async.wait_group 0;" ::: "memory");
        }
        __syncthreads();   // chunk c visible to all threads

        const char* Bh = smc + OFF_B + (c & 1) * 65536 + nh * 32768;
        const char* Bl = Bh + 16384;

        #pragma unroll
        for (int kkc = 0; kkc < 4; kkc++) {
            const int ks = c * 4 + kkc;
            const int kb = ks * 8 + acol;
            uint32_t ah[4];
            ah[0] = Ahi[(arow + 0) * AS_U32 + kb + 0];
            ah[1] = Ahi[(arow + 8) * AS_U32 + kb + 0];
            ah[2] = Ahi[(arow + 0) * AS_U32 + kb + 4];
            ah[3] = Ahi[(arow + 8) * AS_U32 + kb + 4];
            #pragma unroll
            for (int nf = 0; nf < 16; nf++) {
                const int boff = ((kkc * 16 + nf) * 32 + lane) * 8;
                uint2 bh = *(const uint2*)(Bh + boff);
                uint2 bl = *(const uint2*)(Bl + boff);
                mma_hff(acc[nf], ah, bh.x, bh.y);
                mma_hff(acc[nf], ah, bl.x, bl.y);
            }
        }
    }

    // ---- Epilogue
    {
        const int gr = row0 + wp * 16 + arow;
        float* o0 = out + (size_t)gr * 256;
        float* o1 = o0 + 8 * 256;
        const float* b2s = smf + OFF_B2 / 4;
        #pragma unroll
        for (int nf = 0; nf < 16; nf++) {
            const int col = nh * 128 + nf * 8 + (lane & 3) * 2;
            float bx = b2s[col], by = b2s[col + 1];
            float2 v0 = make_float2(acc[nf][0] + bx, acc[nf][1] + by);
            float2 v1 = make_float2(acc[nf][2] + bx, acc[nf][3] + by);
            *(float2*)(o0 + col) = v0;
            *(float2*)(o1 + col) = v1;
        }
    }
}

// ---------------------------------------------------------------------------

extern "C" void kernel_launch(void* const* d_in, const int* in_sizes, int n_in,
                              void* d_out, int out_size) {
    const float* vel   = (const float*)d_in[0];
    const float* dm    = (const float*)d_in[1];
    const float* W1    = (const float*)d_in[2];
    const float* b1    = (const float*)d_in[3];
    const float* gamma = (const float*)d_in[4];
    const float* beta  = (const float*)d_in[5];
    const float* W2    = (const float*)d_in[6];
    const float* b2    = (const float*)d_in[7];
    float* out = (float*)d_out;

    // ncu captures our 4th launch (calibrated R8-R14) -> put topk there.
    w2prep_kernel<<<64, 256>>>(W2);
    noop_kernel<<<1, 32>>>();
    noop_kernel<<<1, 32>>>();
    topk_kernel<<<65536 / (32 * TKW), TKW * 32>>>(dm, vel);

    cudaFuncSetAttribute(mlp_kernel, cudaFuncAttributeMaxDynamicSharedMemorySize,
                         SMEM_MLP);
    mlp_kernel<<<512, 512, SMEM_MLP>>>(W1, b1, gamma, beta, b2, out);
}

// round 16
// speedup vs baseline: 1.1523x; 1.1523x over previous
#include <cuda_runtime.h>
#include <cuda_fp16.h>
#include <cstdint>

typedef unsigned long long ull;
#define FULLMASK 0xFFFFFFFFu

// Scratch for combined features [vx,vy,vz, rx,ry,rz] per row (64*1024 rows).
__device__ float g_comb[64 * 1024 * 6];

// Prepped W2 (B = W2[k][n]) as mma.sync m16n8k16 B-fragment images, fp16 hi/lo.
__device__ __align__(16) unsigned char g_bhi[2 * 4 * 16384];
__device__ __align__(16) unsigned char g_blo[2 * 4 * 16384];

// ---------------------------------------------------------------------------
// Kernel 0: prep W2 -> fp16 hi/lo B-fragment images (runs once per launch).
// ---------------------------------------------------------------------------
__device__ __forceinline__ uint32_t pkh2(float lo, float hi) {
    uint32_t r;
    asm("cvt.rn.f16x2.f32 %0, %1, %2;" : "=r"(r) : "f"(hi), "f"(lo));
    return r;
}
__device__ __forceinline__ void splitf(float x, float &hi, float &lo) {
    __half h = __float2half_rn(x);
    hi = __half2float(h);
    lo = x - hi;
}

__global__ void __launch_bounds__(256) w2prep_kernel(const float* __restrict__ W2) {
    const int gid = blockIdx.x * 256 + threadIdx.x;   // 0..16383
    const int lane = gid & 31;
    const int nf = (gid >> 5) & 31;
    const int kk = gid >> 10;                          // 0..15
    const int k0 = kk * 16 + (lane & 3) * 2;
    const int n  = nf * 8 + (lane >> 2);
    float w00 = W2[(k0 + 0) * 256 + n];
    float w01 = W2[(k0 + 1) * 256 + n];
    float w10 = W2[(k0 + 8) * 256 + n];
    float w11 = W2[(k0 + 9) * 256 + n];
    float h00, l00, h01, l01, h10, l10, h11, l11;
    splitf(w00, h00, l00); splitf(w01, h01, l01);
    splitf(w10, h10, l10); splitf(w11, h11, l11);
    const int nh = nf >> 4, c = kk >> 2, kkc = kk & 3, nfh = nf & 15;
    const size_t off = (size_t)(nh * 4 + c) * 16384
                     + (size_t)(((kkc * 16 + nfh) * 32 + lane) * 8);
    *(uint2*)(g_bhi + off) = make_uint2(pkh2(h00, h01), pkh2(h10, h11));
    *(uint2*)(g_blo + off) = make_uint2(pkh2(l00, l01), pkh2(l10, l11));
}

// ---------------------------------------------------------------------------
// noop: spacer so the 4th launch (ncu's capture slot) is mlp_kernel.
// ---------------------------------------------------------------------------
__global__ void noop_kernel() {}

// ---------------------------------------------------------------------------
// Kernel 1: top-4 smallest distances per row -> combined features.
// R16: each ROW is split across 2 warps (column halves) to double the total
// warp count (2048 -> 4096; occupancy was the measured ceiling at 13.8%).
// Lane-per-row within a half; cp.async 4-stage pipeline on 32x16 tiles
// (stride-5 float4 padding, phase-conflict-free). fp32 prefilter guards the
// exact u64 insert; per-row halves merged exactly via smem at the end.
// Keys ((u32)bits<<32)|global_idx == exact JAX (value asc, index asc) order.
// ---------------------------------------------------------------------------

__device__ __forceinline__ void cswap_u64(ull &a, ull &b) {
    if (b < a) { ull t = a; a = b; b = t; }
}

#define TK_ST 4         // pipeline stages
#define TK_TILES 32     // 512 cols per warp / 16
#define TK_STG (32 * 5) // float4s per stage (stride-5 pad)

__global__ void __launch_bounds__(64) topk_kernel(
    const float* __restrict__ dm, const float* __restrict__ vel)
{
    __shared__ float4 tile[2][TK_ST][TK_STG];
    __shared__ ull mk[4][33];      // warp 1's per-row sorted top-4

    const int warp = threadIdx.x >> 5;
    const int lane = threadIdx.x & 31;
    const int row0 = blockIdx.x * 32;
    const int col0 = warp * 512;
    const int myrow = row0 + lane;
    const float* base = dm + (size_t)row0 * 1024 + col0;

    const ull INIT = ((ull)0x7F800000u << 32) | 0xFFFFFFFFull;
    ull k0 = INIT, k1 = INIT, k2 = INIT, k3 = INIT;
    float t3f = __int_as_float(0x7F800000);

    uint32_t sbase = (uint32_t)__cvta_generic_to_shared(&tile[warp][0][0]);

    // lane -> 4 fixed 16B chunks per tile: ch = lane + 32*i, r = ch/4, cc = ch%4
    #pragma unroll
    for (int p = 0; p < TK_ST - 1; p++) {
        uint32_t dst = sbase + (uint32_t)p * (TK_STG * 16);
        #pragma unroll
        for (int i = 0; i < 4; i++) {
            const int ch = lane + 32 * i;
            const int r = ch >> 2, cc = ch & 3;
            const float* src = base + (size_t)r * 1024 + p * 16 + cc * 4;
            asm volatile("cp.async.cg.shared.global [%0], [%1], 16;"
                         :: "r"(dst + (uint32_t)(r * 5 + cc) * 16u), "l"(src)
                         : "memory");
        }
        asm volatile("cp.async.commit_group;" ::: "memory");
    }

    #pragma unroll 1
    for (int t = 0; t < TK_TILES; t++) {
        if (t + 3 < TK_TILES) {
            const int p = t + 3;
            uint32_t dst = sbase + (uint32_t)(p & (TK_ST - 1)) * (TK_STG * 16);
            #pragma unroll
            for (int i = 0; i < 4; i++) {
                const int ch = lane + 32 * i;
                const int r = ch >> 2, cc = ch & 3;
                const float* src = base + (size_t)r * 1024 + p * 16 + cc * 4;
                asm volatile("cp.async.cg.shared.global [%0], [%1], 16;"
                             :: "r"(dst + (uint32_t)(r * 5 + cc) * 16u), "l"(src)
                             : "memory");
            }
            asm volatile("cp.async.commit_group;" ::: "memory");
            asm volatile("cp.async.wait_group 3;" ::: "memory");
        } else if (t + 3 == TK_TILES) {
            asm volatile("cp.async.wait_group 2;" ::: "memory");
        } else if (t + 2 == TK_TILES) {
            asm volatile("cp.async.wait_group 1;" ::: "memory");
        } else {
            asm volatile("cp.async.wait_group 0;" ::: "memory");
        }
        __syncwarp();

        // scan own row (row index = lane) in tile t
        const float4* myr = &tile[warp][t & (TK_ST - 1)][lane * 5];
        #pragma unroll
        for (int c = 0; c < 4; c++) {
            float4 v = myr[c];
            float mn = fminf(fminf(v.x, v.y), fminf(v.z, v.w));
            if (mn <= t3f) {
                const int jb = col0 + t * 16 + c * 4;
                float e[4] = {v.x, v.y, v.z, v.w};
                #pragma unroll
                for (int q = 0; q < 4; q++) {
                    if (e[q] <= t3f) {
                        ull key = ((ull)__float_as_uint(e[q]) << 32) | (unsigned)(jb + q);
                        if (key < k3) {
                            k3 = key;
                            cswap_u64(k2, k3);
                            cswap_u64(k1, k2);
                            cswap_u64(k0, k1);
                            t3f = __uint_as_float((unsigned)(k3 >> 32));
                        }
                    }
                }
            }
        }
        __syncwarp();
    }

    // ---- merge the two column halves per row (exact u64 merge)
    if (warp == 1) {
        mk[0][lane] = k0; mk[1][lane] = k1; mk[2][lane] = k2; mk[3][lane] = k3;
    }
    __syncthreads();
    if (warp == 0) {
        #pragma unroll
        for (int i = 0; i < 4; i++) {
            ull m = mk[i][lane];
            if (m < k3) {
                k3 = m;
                cswap_u64(k2, k3);
                cswap_u64(k1, k2);
                cswap_u64(k0, k1);
            }
        }

        const int b = myrow >> 10;
        const int a = myrow & 1023;
        const float* vb = vel + (size_t)b * (1024 * 3);
        const int i1 = (int)(unsigned)k1;
        const int i2 = (int)(unsigned)k2;
        const int i3 = (int)(unsigned)k3;
        float sx = vb[a * 3 + 0], sy = vb[a * 3 + 1], sz = vb[a * 3 + 2];
        float nx = vb[i1 * 3 + 0] + vb[i2 * 3 + 0] + vb[i3 * 3 + 0];
        float ny = vb[i1 * 3 + 1] + vb[i2 * 3 + 1] + vb[i3 * 3 + 1];
        float nz = vb[i1 * 3 + 2] + vb[i2 * 3 + 2] + vb[i3 * 3 + 2];
        const float third = 1.0f / 3.0f;
        float* c = g_comb + (size_t)myrow * 6;
        c[0] = sx; c[1] = sy; c[2] = sz;
        c[3] = sx - nx * third;
        c[4] = sy - ny * third;
        c[5] = sz - nz * third;
    }
}

// ---------------------------------------------------------------------------
// Kernel 2: fused MLP (unchanged from R15): GEMM1+ReLU+LN fp32, GEMM2 on
// tensor cores (2-MMA fp16 split), B-chunk images double-buffered via cp.async.
// ---------------------------------------------------------------------------

#define AS_U32 132
#define A_BYTES (128 * AS_U32 * 4)

#define OFF_W1   0
#define OFF_B1   6144
#define OFF_G    7168
#define OFF_BT   8192
#define OFF_B2   9216
#define OFF_CMB  10240
#define OFF_AHI  13312
#define OFF_B    (OFF_AHI + A_BYTES)     // 80896: 2 buffers x 64KB
#define SMEM_MLP (OFF_B + 131072)        // 211968

__device__ __forceinline__ void mma_hff(float d[4], const uint32_t a[4],
                                        uint32_t b0, uint32_t b1) {
    asm volatile(
        "mma.sync.aligned.m16n8k16.row.col.f32.f16.f16.f32 "
        "{%0,%1,%2,%3}, {%4,%5,%6,%7}, {%8,%9}, {%0,%1,%2,%3};"
        : "+f"(d[0]), "+f"(d[1]), "+f"(d[2]), "+f"(d[3])
        : "r"(a[0]), "r"(a[1]), "r"(a[2]), "r"(a[3]), "r"(b0), "r"(b1));
}

__device__ __forceinline__ void issue_b_chunk(char* smc, int c, int buf, int t) {
    const unsigned char* srcs[4] = {
        g_bhi + (size_t)c * 16384,
        g_blo + (size_t)c * 16384,
        g_bhi + (size_t)(4 + c) * 16384,
        g_blo + (size_t)(4 + c) * 16384
    };
    uint32_t dstb = (uint32_t)__cvta_generic_to_shared(smc + OFF_B)
                  + (uint32_t)buf * 65536u + (uint32_t)t * 32u;
    #pragma unroll
    for (int img = 0; img < 4; img++) {
        const unsigned char* s = srcs[img] + t * 32;
        uint32_t d = dstb + (uint32_t)img * 16384u;
        asm volatile("cp.async.cg.shared.global [%0], [%1], 16;"
                     :: "r"(d), "l"(s) : "memory");
        asm volatile("cp.async.cg.shared.global [%0], [%1], 16;"
                     :: "r"(d + 16u), "l"(s + 16) : "memory");
    }
    asm volatile("cp.async.commit_group;" ::: "memory");
}

__global__ void __launch_bounds__(512) mlp_kernel(
    const float* __restrict__ W1, const float* __restrict__ b1,
    const float* __restrict__ gamma, const float* __restrict__ beta,
    const float* __restrict__ b2, float* __restrict__ out)
{
    extern __shared__ char smc[];
    float* smf = (float*)smc;

    const int t = threadIdx.x;
    const int wid = t >> 5;
    const int lane = t & 31;
    const int row0 = blockIdx.x * 128;

    issue_b_chunk(smc, 0, 0, t);

    for (int i = t; i < 6 * 256; i += 512) smf[OFF_W1 / 4 + i] = W1[i];
    if (t < 256) {
        smf[OFF_B1 / 4 + t] = b1[t];
        smf[OFF_G  / 4 + t] = gamma[t];
        smf[OFF_BT / 4 + t] = beta[t];
        smf[OFF_B2 / 4 + t] = b2[t];
    }
    for (int i = t; i < 128 * 6; i += 512)
        smf[OFF_CMB / 4 + i] = g_comb[(size_t)row0 * 6 + i];
    __syncthreads();

    // ---- Phase A
    {
        const int r = t >> 2;
        const int q = t & 3;
        const float* cm = smf + OFF_CMB / 4 + r * 6;
        const float c0 = cm[0], c1 = cm[1], c2 = cm[2];
        const float c3 = cm[3], c4 = cm[4], c5 = cm[5];
        const float2* w1v = (const float2*)(smc + OFF_W1);
        const float2* b1v = (const float2*)(smc + OFF_B1);

        float xs0[32], xs1[32];
        float sum = 0.f, sq = 0.f;
        #pragma unroll
        for (int pe = 0; pe < 32; pe++) {
            const int pidx = 4 * pe + q;
            float2 bp = b1v[pidx];
            float x0 = bp.x, x1 = bp.y;
            float2 w;
            w = w1v[0 * 128 + pidx]; x0 = fmaf(c0, w.x, x0); x1 = fmaf(c0, w.y, x1);
            w = w1v[1 * 128 + pidx]; x0 = fmaf(c1, w.x, x0); x1 = fmaf(c1, w.y, x1);
            w = w1v[2 * 128 + pidx]; x0 = fmaf(c2, w.x, x0); x1 = fmaf(c2, w.y, x1);
            w = w1v[3 * 128 + pidx]; x0 = fmaf(c3, w.x, x0); x1 = fmaf(c3, w.y, x1);
            w = w1v[4 * 128 + pidx]; x0 = fmaf(c4, w.x, x0); x1 = fmaf(c4, w.y, x1);
            w = w1v[5 * 128 + pidx]; x0 = fmaf(c5, w.x, x0); x1 = fmaf(c5, w.y, x1);
            x0 = fmaxf(x0, 0.f);
            x1 = fmaxf(x1, 0.f);
            sum += x0 + x1;
            sq = fmaf(x0, x0, fmaf(x1, x1, sq));
            xs0[pe] = x0;
            xs1[pe] = x1;
        }
        sum += __shfl_xor_sync(FULLMASK, sum, 1);
        sq  += __shfl_xor_sync(FULLMASK, sq, 1);
        sum += __shfl_xor_sync(FULLMASK, sum, 2);
        sq  += __shfl_xor_sync(FULLMASK, sq, 2);
        const float mu   = sum * (1.f / 256.f);
        const float var  = sq * (1.f / 256.f) - mu * mu;
        const float rstd = rsqrtf(var + 1e-5f);

        const float2* gv2 = (const float2*)(smc + OFF_G);
        const float2* bt2 = (const float2*)(smc + OFF_BT);
        uint32_t* ahi = (uint32_t*)(smc + OFF_AHI) + r * AS_U32;
        #pragma unroll
        for (int pe = 0; pe < 32; pe++) {
            const int pidx = 4 * pe + q;
            float2 gp = gv2[pidx];
            float2 tp = bt2[pidx];
            float y0 = fmaf((xs0[pe] - mu) * rstd, gp.x, tp.x);
            float y1 = fmaf((xs1[pe] - mu) * rstd, gp.y, tp.y);
            ahi[pidx] = pkh2(y0, y1);
        }
    }

    // ---- Phase B
    const int wp = wid & 7;
    const int nh = wid >> 3;
    const uint32_t* Ahi = (const uint32_t*)(smc + OFF_AHI) + wp * 16 * AS_U32;
    const int arow = (lane >> 2);
    const int acol = (lane & 3);

    float acc[16][4];
    #pragma unroll
    for (int nf = 0; nf < 16; nf++)
        #pragma unroll
        for (int j = 0; j < 4; j++) acc[nf][j] = 0.f;

    #pragma unroll 1
    for (int c = 0; c < 4; c++) {
        __syncthreads();
        if (c < 3) {
            issue_b_chunk(smc, c + 1, (c + 1) & 1, t);
            asm volatile("cp.async.wait_group 1;" ::: "memory");
        } else {
            asm volatile("cp.async.wait_group 0;" ::: "memory");
        }
        __syncthreads();

        const char* Bh = smc + OFF_B + (c & 1) * 65536 + nh * 32768;
        const char* Bl = Bh + 16384;

        #pragma unroll
        for (int kkc = 0; kkc < 4; kkc++) {
            const int ks = c * 4 + kkc;
            const int kb = ks * 8 + acol;
            uint32_t ah[4];
            ah[0] = Ahi[(arow + 0) * AS_U32 + kb + 0];
            ah[1] = Ahi[(arow + 8) * AS_U32 + kb + 0];
            ah[2] = Ahi[(arow + 0) * AS_U32 + kb + 4];
            ah[3] = Ahi[(arow + 8) * AS_U32 + kb + 4];
            #pragma unroll
            for (int nf = 0; nf < 16; nf++) {
                const int boff = ((kkc * 16 + nf) * 32 + lane) * 8;
                uint2 bh = *(const uint2*)(Bh + boff);
                uint2 bl = *(const uint2*)(Bl + boff);
                mma_hff(acc[nf], ah, bh.x, bh.y);
                mma_hff(acc[nf], ah, bl.x, bl.y);
            }
        }
    }

    // ---- Epilogue
    {
        const int gr = row0 + wp * 16 + arow;
        float* o0 = out + (size_t)gr * 256;
        float* o1 = o0 + 8 * 256;
        const float* b2s = smf + OFF_B2 / 4;
        #pragma unroll
        for (int nf = 0; nf < 16; nf++) {
            const int col = nh * 128 + nf * 8 + (lane & 3) * 2;
            float bx = b2s[col], by = b2s[col + 1];
            float2 v0 = make_float2(acc[nf][0] + bx, acc[nf][1] + by);
            float2 v1 = make_float2(acc[nf][2] + bx, acc[nf][3] + by);
            *(float2*)(o0 + col) = v0;
            *(float2*)(o1 + col) = v1;
        }
    }
}

// ---------------------------------------------------------------------------

extern "C" void kernel_launch(void* const* d_in, const int* in_sizes, int n_in,
                              void* d_out, int out_size) {
    const float* vel   = (const float*)d_in[0];
    const float* dm    = (const float*)d_in[1];
    const float* W1    = (const float*)d_in[2];
    const float* b1    = (const float*)d_in[3];
    const float* gamma = (const float*)d_in[4];
    const float* beta  = (const float*)d_in[5];
    const float* W2    = (const float*)d_in[6];
    const float* b2    = (const float*)d_in[7];
    float* out = (float*)d_out;

    // slot 4 (ncu capture) = mlp this round.
    w2prep_kernel<<<64, 256>>>(W2);
    noop_kernel<<<1, 32>>>();
    topk_kernel<<<2048, 64>>>(dm, vel);

    cudaFuncSetAttribute(mlp_kernel, cudaFuncAttributeMaxDynamicSharedMemorySize,
                         SMEM_MLP);
    mlp_kernel<<<512, 512, SMEM_MLP>>>(W1, b1, gamma, beta, b2, out);
}

// round 17
// speedup vs baseline: 1.2836x; 1.1140x over previous
#include <cuda_runtime.h>
#include <cuda_fp16.h>
#include <cstdint>

typedef unsigned long long ull;
#define FULLMASK 0xFFFFFFFFu

// Scratch for combined features [vx,vy,vz, rx,ry,rz] per row (64*1024 rows).
__device__ float g_comb[64 * 1024 * 6];

// Prepped W2 (B = W2[k][n]) as mma.sync m16n8k16 B-fragment images, fp16 hi/lo.
// (lo images retained but no longer consumed by mlp — single-MMA fp16 W2.)
__device__ __align__(16) unsigned char g_bhi[2 * 4 * 16384];
__device__ __align__(16) unsigned char g_blo[2 * 4 * 16384];

// ---------------------------------------------------------------------------
// Kernel 0: prep W2 -> fp16 B-fragment images (runs once per launch).
// ---------------------------------------------------------------------------
__device__ __forceinline__ uint32_t pkh2(float lo, float hi) {
    uint32_t r;
    asm("cvt.rn.f16x2.f32 %0, %1, %2;" : "=r"(r) : "f"(hi), "f"(lo));
    return r;
}
__device__ __forceinline__ void splitf(float x, float &hi, float &lo) {
    __half h = __float2half_rn(x);
    hi = __half2float(h);
    lo = x - hi;
}

__global__ void __launch_bounds__(256) w2prep_kernel(const float* __restrict__ W2) {
    const int gid = blockIdx.x * 256 + threadIdx.x;   // 0..16383
    const int lane = gid & 31;
    const int nf = (gid >> 5) & 31;
    const int kk = gid >> 10;                          // 0..15
    const int k0 = kk * 16 + (lane & 3) * 2;
    const int n  = nf * 8 + (lane >> 2);
    float w00 = W2[(k0 + 0) * 256 + n];
    float w01 = W2[(k0 + 1) * 256 + n];
    float w10 = W2[(k0 + 8) * 256 + n];
    float w11 = W2[(k0 + 9) * 256 + n];
    float h00, l00, h01, l01, h10, l10, h11, l11;
    splitf(w00, h00, l00); splitf(w01, h01, l01);
    splitf(w10, h10, l10); splitf(w11, h11, l11);
    const int nh = nf >> 4, c = kk >> 2, kkc = kk & 3, nfh = nf & 15;
    const size_t off = (size_t)(nh * 4 + c) * 16384
                     + (size_t)(((kkc * 16 + nfh) * 32 + lane) * 8);
    *(uint2*)(g_bhi + off) = make_uint2(pkh2(h00, h01), pkh2(h10, h11));
    *(uint2*)(g_blo + off) = make_uint2(pkh2(l00, l01), pkh2(l10, l11));
}

// ---------------------------------------------------------------------------
// noop: spacers so the 4th launch (ncu's capture slot) is topk_kernel.
// ---------------------------------------------------------------------------
__global__ void noop_kernel() {}

// ---------------------------------------------------------------------------
// Kernel 1: top-4 smallest distances per row -> combined features.
// (FROZEN from R16: row split across 2 warps by column half; lane-per-row;
// cp.async 4-stage pipeline on 32x16 tiles; fp32 prefilter; exact u64 merge.)
// ---------------------------------------------------------------------------

__device__ __forceinline__ void cswap_u64(ull &a, ull &b) {
    if (b < a) { ull t = a; a = b; b = t; }
}

#define TK_ST 4         // pipeline stages
#define TK_TILES 32     // 512 cols per warp / 16
#define TK_STG (32 * 5) // float4s per stage (stride-5 pad)

__global__ void __launch_bounds__(64) topk_kernel(
    const float* __restrict__ dm, const float* __restrict__ vel)
{
    __shared__ float4 tile[2][TK_ST][TK_STG];
    __shared__ ull mk[4][33];      // warp 1's per-row sorted top-4

    const int warp = threadIdx.x >> 5;
    const int lane = threadIdx.x & 31;
    const int row0 = blockIdx.x * 32;
    const int col0 = warp * 512;
    const int myrow = row0 + lane;
    const float* base = dm + (size_t)row0 * 1024 + col0;

    const ull INIT = ((ull)0x7F800000u << 32) | 0xFFFFFFFFull;
    ull k0 = INIT, k1 = INIT, k2 = INIT, k3 = INIT;
    float t3f = __int_as_float(0x7F800000);

    uint32_t sbase = (uint32_t)__cvta_generic_to_shared(&tile[warp][0][0]);

    #pragma unroll
    for (int p = 0; p < TK_ST - 1; p++) {
        uint32_t dst = sbase + (uint32_t)p * (TK_STG * 16);
        #pragma unroll
        for (int i = 0; i < 4; i++) {
            const int ch = lane + 32 * i;
            const int r = ch >> 2, cc = ch & 3;
            const float* src = base + (size_t)r * 1024 + p * 16 + cc * 4;
            asm volatile("cp.async.cg.shared.global [%0], [%1], 16;"
                         :: "r"(dst + (uint32_t)(r * 5 + cc) * 16u), "l"(src)
                         : "memory");
        }
        asm volatile("cp.async.commit_group;" ::: "memory");
    }

    #pragma unroll 1
    for (int t = 0; t < TK_TILES; t++) {
        if (t + 3 < TK_TILES) {
            const int p = t + 3;
            uint32_t dst = sbase + (uint32_t)(p & (TK_ST - 1)) * (TK_STG * 16);
            #pragma unroll
            for (int i = 0; i < 4; i++) {
                const int ch = lane + 32 * i;
                const int r = ch >> 2, cc = ch & 3;
                const float* src = base + (size_t)r * 1024 + p * 16 + cc * 4;
                asm volatile("cp.async.cg.shared.global [%0], [%1], 16;"
                             :: "r"(dst + (uint32_t)(r * 5 + cc) * 16u), "l"(src)
                             : "memory");
            }
            asm volatile("cp.async.commit_group;" ::: "memory");
            asm volatile("cp.async.wait_group 3;" ::: "memory");
        } else if (t + 3 == TK_TILES) {
            asm volatile("cp.async.wait_group 2;" ::: "memory");
        } else if (t + 2 == TK_TILES) {
            asm volatile("cp.async.wait_group 1;" ::: "memory");
        } else {
            asm volatile("cp.async.wait_group 0;" ::: "memory");
        }
        __syncwarp();

        const float4* myr = &tile[warp][t & (TK_ST - 1)][lane * 5];
        #pragma unroll
        for (int c = 0; c < 4; c++) {
            float4 v = myr[c];
            float mn = fminf(fminf(v.x, v.y), fminf(v.z, v.w));
            if (mn <= t3f) {
                const int jb = col0 + t * 16 + c * 4;
                float e[4] = {v.x, v.y, v.z, v.w};
                #pragma unroll
                for (int q = 0; q < 4; q++) {
                    if (e[q] <= t3f) {
                        ull key = ((ull)__float_as_uint(e[q]) << 32) | (unsigned)(jb + q);
                        if (key < k3) {
                            k3 = key;
                            cswap_u64(k2, k3);
                            cswap_u64(k1, k2);
                            cswap_u64(k0, k1);
                            t3f = __uint_as_float((unsigned)(k3 >> 32));
                        }
                    }
                }
            }
        }
        __syncwarp();
    }

    if (warp == 1) {
        mk[0][lane] = k0; mk[1][lane] = k1; mk[2][lane] = k2; mk[3][lane] = k3;
    }
    __syncthreads();
    if (warp == 0) {
        #pragma unroll
        for (int i = 0; i < 4; i++) {
            ull m = mk[i][lane];
            if (m < k3) {
                k3 = m;
                cswap_u64(k2, k3);
                cswap_u64(k1, k2);
                cswap_u64(k0, k1);
            }
        }

        const int b = myrow >> 10;
        const int a = myrow & 1023;
        const float* vb = vel + (size_t)b * (1024 * 3);
        const int i1 = (int)(unsigned)k1;
        const int i2 = (int)(unsigned)k2;
        const int i3 = (int)(unsigned)k3;
        float sx = vb[a * 3 + 0], sy = vb[a * 3 + 1], sz = vb[a * 3 + 2];
        float nx = vb[i1 * 3 + 0] + vb[i2 * 3 + 0] + vb[i3 * 3 + 0];
        float ny = vb[i1 * 3 + 1] + vb[i2 * 3 + 1] + vb[i3 * 3 + 1];
        float nz = vb[i1 * 3 + 2] + vb[i2 * 3 + 2] + vb[i3 * 3 + 2];
        const float third = 1.0f / 3.0f;
        float* c = g_comb + (size_t)myrow * 6;
        c[0] = sx; c[1] = sy; c[2] = sz;
        c[3] = sx - nx * third;
        c[4] = sy - ny * third;
        c[5] = sz - nz * third;
    }
}

// ---------------------------------------------------------------------------
// Kernel 2: fused MLP. GEMM1+ReLU+LN fp32; GEMM2 = SINGLE fp16 MMA per
// fragment (A = rn16(h), B = rn16(W2)). Halves tensor work, B LDS traffic
// (the measured 60.9% L1 pipe), and B smem vs R16. Error model: A-rounding
// (measured 2.12e-4) + B-rounding (same structure, ~2-3e-4) => ~3-4.5e-4.
// B-chunk images double-buffered via cp.async as before.
// ---------------------------------------------------------------------------

#define AS_U32 132
#define A_BYTES (128 * AS_U32 * 4)

#define OFF_W1   0
#define OFF_B1   6144
#define OFF_G    7168
#define OFF_BT   8192
#define OFF_B2   9216
#define OFF_CMB  10240
#define OFF_AHI  13312
#define OFF_B    (OFF_AHI + A_BYTES)     // 80896: 2 buffers x 32KB
#define SMEM_MLP (OFF_B + 65536)         // 146432

__device__ __forceinline__ void mma_hff(float d[4], const uint32_t a[4],
                                        uint32_t b0, uint32_t b1) {
    asm volatile(
        "mma.sync.aligned.m16n8k16.row.col.f32.f16.f16.f32 "
        "{%0,%1,%2,%3}, {%4,%5,%6,%7}, {%8,%9}, {%0,%1,%2,%3};"
        : "+f"(d[0]), "+f"(d[1]), "+f"(d[2]), "+f"(d[3])
        : "r"(a[0]), "r"(a[1]), "r"(a[2]), "r"(a[3]), "r"(b0), "r"(b1));
}

// issue async copy of k-chunk c's two 16KB B-hi images into buffer buf
__device__ __forceinline__ void issue_b_chunk(char* smc, int c, int buf, int t) {
    const unsigned char* s0 = g_bhi + (size_t)c * 16384 + t * 32;        // nh0
    const unsigned char* s1 = g_bhi + (size_t)(4 + c) * 16384 + t * 32;  // nh1
    uint32_t dstb = (uint32_t)__cvta_generic_to_shared(smc + OFF_B)
                  + (uint32_t)buf * 32768u + (uint32_t)t * 32u;
    asm volatile("cp.async.cg.shared.global [%0], [%1], 16;"
                 :: "r"(dstb), "l"(s0) : "memory");
    asm volatile("cp.async.cg.shared.global [%0], [%1], 16;"
                 :: "r"(dstb + 16u), "l"(s0 + 16) : "memory");
    asm volatile("cp.async.cg.shared.global [%0], [%1], 16;"
                 :: "r"(dstb + 16384u), "l"(s1) : "memory");
    asm volatile("cp.async.cg.shared.global [%0], [%1], 16;"
                 :: "r"(dstb + 16400u), "l"(s1 + 16) : "memory");
    asm volatile("cp.async.commit_group;" ::: "memory");
}

__global__ void __launch_bounds__(512) mlp_kernel(
    const float* __restrict__ W1, const float* __restrict__ b1,
    const float* __restrict__ gamma, const float* __restrict__ beta,
    const float* __restrict__ b2, float* __restrict__ out)
{
    extern __shared__ char smc[];
    float* smf = (float*)smc;

    const int t = threadIdx.x;
    const int wid = t >> 5;
    const int lane = t & 31;
    const int row0 = blockIdx.x * 128;

    issue_b_chunk(smc, 0, 0, t);

    for (int i = t; i < 6 * 256; i += 512) smf[OFF_W1 / 4 + i] = W1[i];
    if (t < 256) {
        smf[OFF_B1 / 4 + t] = b1[t];
        smf[OFF_G  / 4 + t] = gamma[t];
        smf[OFF_BT / 4 + t] = beta[t];
        smf[OFF_B2 / 4 + t] = b2[t];
    }
    for (int i = t; i < 128 * 6; i += 512)
        smf[OFF_CMB / 4 + i] = g_comb[(size_t)row0 * 6 + i];
    __syncthreads();

    // ---- Phase A: GEMM1+relu (x in regs), LN, fp16 -> smem
    {
        const int r = t >> 2;
        const int q = t & 3;
        const float* cm = smf + OFF_CMB / 4 + r * 6;
        const float c0 = cm[0], c1 = cm[1], c2 = cm[2];
        const float c3 = cm[3], c4 = cm[4], c5 = cm[5];
        const float2* w1v = (const float2*)(smc + OFF_W1);
        const float2* b1v = (const float2*)(smc + OFF_B1);

        float xs0[32], xs1[32];
        float sum = 0.f, sq = 0.f;
        #pragma unroll
        for (int pe = 0; pe < 32; pe++) {
            const int pidx = 4 * pe + q;
            float2 bp = b1v[pidx];
            float x0 = bp.x, x1 = bp.y;
            float2 w;
            w = w1v[0 * 128 + pidx]; x0 = fmaf(c0, w.x, x0); x1 = fmaf(c0, w.y, x1);
            w = w1v[1 * 128 + pidx]; x0 = fmaf(c1, w.x, x0); x1 = fmaf(c1, w.y, x1);
            w = w1v[2 * 128 + pidx]; x0 = fmaf(c2, w.x, x0); x1 = fmaf(c2, w.y, x1);
            w = w1v[3 * 128 + pidx]; x0 = fmaf(c3, w.x, x0); x1 = fmaf(c3, w.y, x1);
            w = w1v[4 * 128 + pidx]; x0 = fmaf(c4, w.x, x0); x1 = fmaf(c4, w.y, x1);
            w = w1v[5 * 128 + pidx]; x0 = fmaf(c5, w.x, x0); x1 = fmaf(c5, w.y, x1);
            x0 = fmaxf(x0, 0.f);
            x1 = fmaxf(x1, 0.f);
            sum += x0 + x1;
            sq = fmaf(x0, x0, fmaf(x1, x1, sq));
            xs0[pe] = x0;
            xs1[pe] = x1;
        }
        sum += __shfl_xor_sync(FULLMASK, sum, 1);
        sq  += __shfl_xor_sync(FULLMASK, sq, 1);
        sum += __shfl_xor_sync(FULLMASK, sum, 2);
        sq  += __shfl_xor_sync(FULLMASK, sq, 2);
        const float mu   = sum * (1.f / 256.f);
        const float var  = sq * (1.f / 256.f) - mu * mu;
        const float rstd = rsqrtf(var + 1e-5f);

        const float2* gv2 = (const float2*)(smc + OFF_G);
        const float2* bt2 = (const float2*)(smc + OFF_BT);
        uint32_t* ahi = (uint32_t*)(smc + OFF_AHI) + r * AS_U32;
        #pragma unroll
        for (int pe = 0; pe < 32; pe++) {
            const int pidx = 4 * pe + q;
            float2 gp = gv2[pidx];
            float2 tp = bt2[pidx];
            float y0 = fmaf((xs0[pe] - mu) * rstd, gp.x, tp.x);
            float y1 = fmaf((xs1[pe] - mu) * rstd, gp.y, tp.y);
            ahi[pidx] = pkh2(y0, y1);
        }
    }

    // ---- Phase B: out = h @ W2 + b2 (single fp16 MMA per fragment)
    const int wp = wid & 7;
    const int nh = wid >> 3;
    const uint32_t* Ahi = (const uint32_t*)(smc + OFF_AHI) + wp * 16 * AS_U32;
    const int arow = (lane >> 2);
    const int acol = (lane & 3);

    float acc[16][4];
    #pragma unroll
    for (int nf = 0; nf < 16; nf++)
        #pragma unroll
        for (int j = 0; j < 4; j++) acc[nf][j] = 0.f;

    #pragma unroll 1
    for (int c = 0; c < 4; c++) {
        __syncthreads();
        if (c < 3) {
            issue_b_chunk(smc, c + 1, (c + 1) & 1, t);
            asm volatile("cp.async.wait_group 1;" ::: "memory");
        } else {
            asm volatile("cp.async.wait_group 0;" ::: "memory");
        }
        __syncthreads();

        const char* Bh = smc + OFF_B + (c & 1) * 32768 + nh * 16384;

        #pragma unroll
        for (int kkc = 0; kkc < 4; kkc++) {
            const int ks = c * 4 + kkc;
            const int kb = ks * 8 + acol;
            uint32_t ah[4];
            ah[0] = Ahi[(arow + 0) * AS_U32 + kb + 0];
            ah[1] = Ahi[(arow + 8) * AS_U32 + kb + 0];
            ah[2] = Ahi[(arow + 0) * AS_U32 + kb + 4];
            ah[3] = Ahi[(arow + 8) * AS_U32 + kb + 4];
            #pragma unroll
            for (int nf = 0; nf < 16; nf++) {
                const int boff = ((kkc * 16 + nf) * 32 + lane) * 8;
                uint2 bh = *(const uint2*)(Bh + boff);
                mma_hff(acc[nf], ah, bh.x, bh.y);
            }
        }
    }

    // ---- Epilogue
    {
        const int gr = row0 + wp * 16 + arow;
        float* o0 = out + (size_t)gr * 256;
        float* o1 = o0 + 8 * 256;
        const float* b2s = smf + OFF_B2 / 4;
        #pragma unroll
        for (int nf = 0; nf < 16; nf++) {
            const int col = nh * 128 + nf * 8 + (lane & 3) * 2;
            float bx = b2s[col], by = b2s[col + 1];
            float2 v0 = make_float2(acc[nf][0] + bx, acc[nf][1] + by);
            float2 v1 = make_float2(acc[nf][2] + bx, acc[nf][3] + by);
            *(float2*)(o0 + col) = v0;
            *(float2*)(o1 + col) = v1;
        }
    }
}

// ---------------------------------------------------------------------------

extern "C" void kernel_launch(void* const* d_in, const int* in_sizes, int n_in,
                              void* d_out, int out_size) {
    const float* vel   = (const float*)d_in[0];
    const float* dm    = (const float*)d_in[1];
    const float* W1    = (const float*)d_in[2];
    const float* b1    = (const float*)d_in[3];
    const float* gamma = (const float*)d_in[4];
    const float* beta  = (const float*)d_in[5];
    const float* W2    = (const float*)d_in[6];
    const float* b2    = (const float*)d_in[7];
    float* out = (float*)d_out;

    // slot 4 (ncu capture) = topk this round.
    w2prep_kernel<<<64, 256>>>(W2);
    noop_kernel<<<1, 32>>>();
    noop_kernel<<<1, 32>>>();
    topk_kernel<<<2048, 64>>>(dm, vel);

    cudaFuncSetAttribute(mlp_kernel, cudaFuncAttributeMaxDynamicSharedMemorySize,
                         SMEM_MLP);
    mlp_kernel<<<512, 512, SMEM_MLP>>>(W1, b1, gamma, beta, b2, out);
}